// round 2
// baseline (speedup 1.0000x reference)
#include <cuda_runtime.h>
#include <math.h>

// Problem dims
constexpr int BB = 32;    // batch
constexpr int LL = 256;   // query positions
constexpr int SS = 64;    // src positions
constexpr int TT = 64;    // trg positions
constexpr int QD = 768;   // query dim
constexpr int FD = 1024;  // feat dim
constexpr int HD = 768;   // hidden dim
constexpr int OD = 768;   // out dim
constexpr int TSD = TT * SS;   // 4096 combined positions
constexpr int XD = QD + HD;    // 1536 concat dim

// Scratch (static device globals: allocation-free per harness rules)
__device__ __align__(16) float g_q[(size_t)BB * LL * HD];          // 25 MB
__device__ __align__(16) float g_skey[(size_t)BB * SS * HD];       // 6.3 MB
__device__ __align__(16) float g_tkey[(size_t)BB * TT * HD];       // 6.3 MB
__device__ __align__(16) float g_rel[(size_t)BB * TSD * HD];       // 403 MB
__device__ __align__(16) float g_scores[(size_t)BB * LL * TSD];    // 134 MB
__device__ __align__(16) float g_x[(size_t)BB * LL * XD];          // 50 MB

// ---------------------------------------------------------------------------
// Generic tiled GEMM, C = act(scale * A@B + bias)
// A: MxK row-major (lda), B: KxN row-major (ldb), C: MxN (ldc)
// 64x64 block tile, 256 threads, 4x4 per thread, BK=16.
// All dims in this problem are multiples of 64/16: no bounds checks.
// ---------------------------------------------------------------------------
__global__ __launch_bounds__(256) void gemm_nn_kernel(
    const float* __restrict__ A, int lda, size_t sA,
    const float* __restrict__ B, int ldb, size_t sB,
    const float* __restrict__ bias,
    float* __restrict__ C, int ldc, size_t sC,
    int K, float scale, int do_relu)
{
    __shared__ __align__(16) float As[16][68];
    __shared__ __align__(16) float Bs[16][64];

    const float* Ab = A + blockIdx.z * sA;
    const float* Bb = B + blockIdx.z * sB;
    float* Cb = C + blockIdx.z * sC;

    const int tid = threadIdx.x;
    const int tm = tid >> 4;          // 0..15 (m group)
    const int tn = tid & 15;          // 0..15 (n group)
    const int bm = blockIdx.y * 64;
    const int bn = blockIdx.x * 64;

    const int arow = tid >> 2;            // 0..63
    const int acg  = (tid & 3) * 4;       // 0,4,8,12
    const int brow = tid >> 4;            // 0..15
    const int bcol = (tid & 15) * 4;      // 0..60

    float acc[4][4] = {};

    for (int k0 = 0; k0 < K; k0 += 16) {
        float4 av = *(const float4*)(Ab + (size_t)(bm + arow) * lda + k0 + acg);
        As[acg + 0][arow] = av.x;
        As[acg + 1][arow] = av.y;
        As[acg + 2][arow] = av.z;
        As[acg + 3][arow] = av.w;
        *(float4*)(&Bs[brow][bcol]) =
            *(const float4*)(Bb + (size_t)(k0 + brow) * ldb + bn + bcol);
        __syncthreads();
#pragma unroll
        for (int kk = 0; kk < 16; kk++) {
            float4 a = *(const float4*)(&As[kk][tm * 4]);
            float4 b = *(const float4*)(&Bs[kk][tn * 4]);
            acc[0][0] += a.x * b.x; acc[0][1] += a.x * b.y; acc[0][2] += a.x * b.z; acc[0][3] += a.x * b.w;
            acc[1][0] += a.y * b.x; acc[1][1] += a.y * b.y; acc[1][2] += a.y * b.z; acc[1][3] += a.y * b.w;
            acc[2][0] += a.z * b.x; acc[2][1] += a.z * b.y; acc[2][2] += a.z * b.z; acc[2][3] += a.z * b.w;
            acc[3][0] += a.w * b.x; acc[3][1] += a.w * b.y; acc[3][2] += a.w * b.z; acc[3][3] += a.w * b.w;
        }
        __syncthreads();
    }

    float4 bv = make_float4(0.f, 0.f, 0.f, 0.f);
    if (bias) bv = *(const float4*)(bias + bn + tn * 4);
#pragma unroll
    for (int i = 0; i < 4; i++) {
        float4 o;
        o.x = acc[i][0] * scale + bv.x;
        o.y = acc[i][1] * scale + bv.y;
        o.z = acc[i][2] * scale + bv.z;
        o.w = acc[i][3] * scale + bv.w;
        if (do_relu) {
            o.x = fmaxf(o.x, 0.f); o.y = fmaxf(o.y, 0.f);
            o.z = fmaxf(o.z, 0.f); o.w = fmaxf(o.w, 0.f);
        }
        *(float4*)(Cb + (size_t)(bm + tm * 4 + i) * ldc + bn + tn * 4) = o;
    }
}

// ---------------------------------------------------------------------------
// NT GEMM: C[m,n] = scale * sum_k A[m,k] * B[n,k]
// A: MxK row-major, B: NxK row-major. Used for scores = q . rel^T.
// ---------------------------------------------------------------------------
__global__ __launch_bounds__(256) void gemm_nt_kernel(
    const float* __restrict__ A, int lda, size_t sA,
    const float* __restrict__ B, int ldb, size_t sB,
    float* __restrict__ C, int ldc, size_t sC,
    int K, float scale)
{
    __shared__ __align__(16) float As[16][68];
    __shared__ __align__(16) float Bs[16][68];

    const float* Ab = A + blockIdx.z * sA;
    const float* Bb = B + blockIdx.z * sB;
    float* Cb = C + blockIdx.z * sC;

    const int tid = threadIdx.x;
    const int tm = tid >> 4;
    const int tn = tid & 15;
    const int bm = blockIdx.y * 64;
    const int bn = blockIdx.x * 64;

    const int row = tid >> 2;         // 0..63
    const int cg  = (tid & 3) * 4;    // 0,4,8,12

    float acc[4][4] = {};

    for (int k0 = 0; k0 < K; k0 += 16) {
        float4 av = *(const float4*)(Ab + (size_t)(bm + row) * lda + k0 + cg);
        As[cg + 0][row] = av.x;
        As[cg + 1][row] = av.y;
        As[cg + 2][row] = av.z;
        As[cg + 3][row] = av.w;
        float4 bw = *(const float4*)(Bb + (size_t)(bn + row) * ldb + k0 + cg);
        Bs[cg + 0][row] = bw.x;
        Bs[cg + 1][row] = bw.y;
        Bs[cg + 2][row] = bw.z;
        Bs[cg + 3][row] = bw.w;
        __syncthreads();
#pragma unroll
        for (int kk = 0; kk < 16; kk++) {
            float4 a = *(const float4*)(&As[kk][tm * 4]);
            float4 b = *(const float4*)(&Bs[kk][tn * 4]);
            acc[0][0] += a.x * b.x; acc[0][1] += a.x * b.y; acc[0][2] += a.x * b.z; acc[0][3] += a.x * b.w;
            acc[1][0] += a.y * b.x; acc[1][1] += a.y * b.y; acc[1][2] += a.y * b.z; acc[1][3] += a.y * b.w;
            acc[2][0] += a.z * b.x; acc[2][1] += a.z * b.y; acc[2][2] += a.z * b.z; acc[2][3] += a.z * b.w;
            acc[3][0] += a.w * b.x; acc[3][1] += a.w * b.y; acc[3][2] += a.w * b.z; acc[3][3] += a.w * b.w;
        }
        __syncthreads();
    }

#pragma unroll
    for (int i = 0; i < 4; i++) {
        float4 o;
        o.x = acc[i][0] * scale;
        o.y = acc[i][1] * scale;
        o.z = acc[i][2] * scale;
        o.w = acc[i][3] * scale;
        *(float4*)(Cb + (size_t)(bm + tm * 4 + i) * ldc + bn + tn * 4) = o;
    }
}

// ---------------------------------------------------------------------------
// rel_key[b,t,s,h] = tanh(s_key[b,s,h] + t_key[b,t,h]); vectorized over h.
// ---------------------------------------------------------------------------
__global__ __launch_bounds__(256) void relkey_kernel(
    const float* __restrict__ skey, const float* __restrict__ tkey,
    float* __restrict__ rel)
{
    const size_t H4 = HD / 4;
    size_t idx = (size_t)blockIdx.x * blockDim.x + threadIdx.x;  // over BB*TT*SS*H4
    size_t h4 = idx % H4;
    size_t rest = idx / H4;
    int s = (int)(rest % SS); rest /= SS;
    int t = (int)(rest % TT);
    int b = (int)(rest / TT);
    float4 sv = ((const float4*)skey)[((size_t)b * SS + s) * H4 + h4];
    float4 tv = ((const float4*)tkey)[((size_t)b * TT + t) * H4 + h4];
    float4 o;
    o.x = tanhf(sv.x + tv.x);
    o.y = tanhf(sv.y + tv.y);
    o.z = tanhf(sv.z + tv.z);
    o.w = tanhf(sv.w + tv.w);
    ((float4*)rel)[idx] = o;
}

// ---------------------------------------------------------------------------
// Softmax over 4096 elements per row; one block (256 threads) per row.
// ---------------------------------------------------------------------------
__global__ __launch_bounds__(256) void softmax_kernel(float* __restrict__ data)
{
    float* row = data + (size_t)blockIdx.x * TSD;
    const int tid = threadIdx.x;
    float v[16];
    float m = -INFINITY;
#pragma unroll
    for (int i = 0; i < 16; i++) {
        v[i] = row[tid + i * 256];
        m = fmaxf(m, v[i]);
    }
#pragma unroll
    for (int o = 16; o; o >>= 1) m = fmaxf(m, __shfl_xor_sync(0xffffffffu, m, o));
    __shared__ float redm[8];
    __shared__ float reds[8];
    if ((tid & 31) == 0) redm[tid >> 5] = m;
    __syncthreads();
#pragma unroll
    for (int w = 0; w < 8; w++) m = fmaxf(m, redm[w]);
    float s = 0.f;
#pragma unroll
    for (int i = 0; i < 16; i++) {
        v[i] = expf(v[i] - m);
        s += v[i];
    }
#pragma unroll
    for (int o = 16; o; o >>= 1) s += __shfl_xor_sync(0xffffffffu, s, o);
    if ((tid & 31) == 0) reds[tid >> 5] = s;
    __syncthreads();
    s = 0.f;
#pragma unroll
    for (int w = 0; w < 8; w++) s += reds[w];
    float inv = 1.f / s;
#pragma unroll
    for (int i = 0; i < 16; i++) row[tid + i * 256] = v[i] * inv;
}

// Copy query into left half of concat buffer x (row stride XD).
__global__ __launch_bounds__(256) void concat_kernel(
    const float* __restrict__ q, float* __restrict__ x)
{
    const size_t Q4 = QD / 4;
    size_t idx = (size_t)blockIdx.x * blockDim.x + threadIdx.x;  // over BB*LL*Q4
    size_t rowi = idx / Q4;
    size_t c4 = idx % Q4;
    ((float4*)x)[rowi * (XD / 4) + c4] = ((const float4*)q)[idx];
}

// ---------------------------------------------------------------------------
extern "C" void kernel_launch(void* const* d_in, const int* in_sizes, int n_in,
                              void* d_out, int out_size)
{
    const float* query = (const float*)d_in[0];
    const float* src   = (const float*)d_in[1];
    const float* trg   = (const float*)d_in[2];
    const float* Wq    = (const float*)d_in[3];
    const float* b_q   = (const float*)d_in[4];
    const float* Ws    = (const float*)d_in[5];
    const float* b_s   = (const float*)d_in[6];
    const float* Wt    = (const float*)d_in[7];
    const float* b_t   = (const float*)d_in[8];
    const float* Wo    = (const float*)d_in[9];
    const float* b_o   = (const float*)d_in[10];
    float* out = (float*)d_out;

    float *q, *skey, *tkey, *rel, *scores, *x;
    cudaGetSymbolAddress((void**)&q, g_q);
    cudaGetSymbolAddress((void**)&skey, g_skey);
    cudaGetSymbolAddress((void**)&tkey, g_tkey);
    cudaGetSymbolAddress((void**)&rel, g_rel);
    cudaGetSymbolAddress((void**)&scores, g_scores);
    cudaGetSymbolAddress((void**)&x, g_x);

    const float inv_sqrt_h = 1.0f / sqrtf((float)HD);
    dim3 blk(256);

    // 1. q = query @ Wq + b_q            (8192 x 768 x 768)
    gemm_nn_kernel<<<dim3(HD / 64, (BB * LL) / 64, 1), blk>>>(
        query, QD, 0, Wq, HD, 0, b_q, q, HD, 0, QD, 1.f, 0);

    // 2. s_key = src @ Ws + b_s          (2048 x 768 x 1024)
    gemm_nn_kernel<<<dim3(HD / 64, (BB * SS) / 64, 1), blk>>>(
        src, FD, 0, Ws, HD, 0, b_s, skey, HD, 0, FD, 1.f, 0);

    // 3. t_key = trg @ Wt + b_t          (2048 x 768 x 1024)
    gemm_nn_kernel<<<dim3(HD / 64, (BB * TT) / 64, 1), blk>>>(
        trg, FD, 0, Wt, HD, 0, b_t, tkey, HD, 0, FD, 1.f, 0);

    // 4. rel_key = tanh(s_key[b,s,:] + t_key[b,t,:])   (32 x 64 x 64 x 768)
    {
        size_t n4 = (size_t)BB * TSD * HD / 4;
        relkey_kernel<<<(unsigned)(n4 / 256), blk>>>(skey, tkey, rel);
    }

    // 5. scores = q . rel^T / sqrt(H)    (batched: 256 x 4096 x 768, z=32)
    gemm_nt_kernel<<<dim3(TSD / 64, LL / 64, BB), blk>>>(
        q, HD, (size_t)LL * HD,
        rel, HD, (size_t)TSD * HD,
        scores, TSD, (size_t)LL * TSD,
        HD, inv_sqrt_h);

    // 6. softmax over 4096 per (b,l) row
    softmax_kernel<<<BB * LL, blk>>>(scores);

    // 7. x[:, :768] = query
    {
        size_t n4 = (size_t)BB * LL * QD / 4;
        concat_kernel<<<(unsigned)(n4 / 256), blk>>>(query, x);
    }

    // 8. x[:, 768:] = scores @ rel       (batched: 256 x 768 x 4096, z=32)
    gemm_nn_kernel<<<dim3(HD / 64, LL / 64, BB), blk>>>(
        scores, TSD, (size_t)LL * TSD,
        rel, HD, (size_t)TSD * HD,
        nullptr,
        x + QD, XD, (size_t)LL * XD,
        TSD, 1.f, 0);

    // 9. out = relu(x @ Wo + b_o)        (8192 x 768 x 1536)
    gemm_nn_kernel<<<dim3(OD / 64, (BB * LL) / 64, 1), blk>>>(
        x, XD, 0, Wo, OD, 0, b_o, out, OD, 0, XD, 1.f, 1);
}

// round 3
// speedup vs baseline: 2.7791x; 2.7791x over previous
#include <cuda_runtime.h>
#include <math.h>
#include <stdint.h>

// Problem dims
constexpr int BB = 32;    // batch
constexpr int LL = 256;   // query positions
constexpr int SS = 64;    // src positions
constexpr int TT = 64;    // trg positions
constexpr int QD = 768;   // query dim
constexpr int FD = 1024;  // feat dim
constexpr int HD = 768;   // hidden dim
constexpr int OD = 768;   // out dim
constexpr int TSD = TT * SS;   // 4096 combined positions
constexpr int XD = QD + HD;    // 1536 concat dim

// Scratch (static device globals: allocation-free per harness rules)
__device__ __align__(16) float g_q[(size_t)BB * LL * HD];
__device__ __align__(16) float g_skey[(size_t)BB * SS * HD];
__device__ __align__(16) float g_tkey[(size_t)BB * TT * HD];
__device__ __align__(16) float g_rel[(size_t)BB * TSD * HD];
__device__ __align__(16) float g_scores[(size_t)BB * LL * TSD];
__device__ __align__(16) float g_x[(size_t)BB * LL * XD];

// ---------------------------------------------------------------------------
// TF32 helpers
// ---------------------------------------------------------------------------
__device__ __forceinline__ uint32_t f2tf32(float f) {
    uint32_t r;
    asm("cvt.rna.tf32.f32 %0, %1;" : "=r"(r) : "f"(f));
    return r;
}

__device__ __forceinline__ void mma8(float* c,
                                     const uint32_t* a,
                                     uint32_t b0, uint32_t b1) {
    asm volatile(
        "mma.sync.aligned.m16n8k8.row.col.f32.tf32.tf32.f32 "
        "{%0,%1,%2,%3}, {%4,%5,%6,%7}, {%8,%9}, {%0,%1,%2,%3};"
        : "+f"(c[0]), "+f"(c[1]), "+f"(c[2]), "+f"(c[3])
        : "r"(a[0]), "r"(a[1]), "r"(a[2]), "r"(a[3]), "r"(b0), "r"(b1));
}

// ---------------------------------------------------------------------------
// TF32 tensor-core GEMM.
//   NT=false: C = act(scale * A(MxK) @ B(KxN) + bias)
//   NT=true : C = act(scale * A(MxK) @ B(NxK)^T + bias)
// Block tile 128x128, BK=32, 256 threads (8 warps, 2m x 4n), warp tile 64x32,
// mma m16n8k8 tf32, fp32 accumulate. All dims multiples of tile sizes.
// Smem strides chosen for conflict-free fragment loads:
//   k-major tiles: row stride 36 -> frag banks = (lane + kbase) mod 32
//   NN B tile [k][n]: row stride 136 -> frag banks = (8k + n) mod 32
// ---------------------------------------------------------------------------
template <bool NT>
__global__ __launch_bounds__(256) void mma_gemm(
    const float* __restrict__ A, int lda, size_t sA,
    const float* __restrict__ B, int ldb, size_t sB,
    const float* __restrict__ bias,
    float* __restrict__ C, int ldc, size_t sC,
    int K, float scale, int do_relu)
{
    __shared__ float sAs[128 * 36];   // 18 KB, [m][k] tf32
    __shared__ float sBs[128 * 36];   // NT: [n][k]; NN uses [k=32][n<=136] = 17.4 KB

    const float* Ab = A + blockIdx.z * sA;
    const float* Bb = B + blockIdx.z * sB;
    float* Cb = C + blockIdx.z * sC;

    const int tid  = threadIdx.x;
    const int lane = tid & 31;
    const int wid  = tid >> 5;
    const int wm   = wid & 1;     // warp m index (0..1) -> 64 rows
    const int wn   = wid >> 1;    // warp n index (0..3) -> 32 cols
    const int bm   = blockIdx.y * 128;
    const int bn   = blockIdx.x * 128;

    float acc[4][4][4] = {};

    for (int k0 = 0; k0 < K; k0 += 32) {
        // ---- A tile: 128 x 32, 1024 float4s, 4 per thread ----
#pragma unroll
        for (int i = 0; i < 4; i++) {
            int r  = (tid >> 3) + 32 * i;
            int c4 = (tid & 7) * 4;
            float4 v = *(const float4*)(Ab + (size_t)(bm + r) * lda + k0 + c4);
            int off = r * 36 + c4;
            sAs[off + 0] = __uint_as_float(f2tf32(v.x));
            sAs[off + 1] = __uint_as_float(f2tf32(v.y));
            sAs[off + 2] = __uint_as_float(f2tf32(v.z));
            sAs[off + 3] = __uint_as_float(f2tf32(v.w));
        }
        // ---- B tile ----
        if (NT) {
            // [n][k] : 128 rows x 32
#pragma unroll
            for (int i = 0; i < 4; i++) {
                int r  = (tid >> 3) + 32 * i;
                int c4 = (tid & 7) * 4;
                float4 v = *(const float4*)(Bb + (size_t)(bn + r) * ldb + k0 + c4);
                int off = r * 36 + c4;
                sBs[off + 0] = __uint_as_float(f2tf32(v.x));
                sBs[off + 1] = __uint_as_float(f2tf32(v.y));
                sBs[off + 2] = __uint_as_float(f2tf32(v.z));
                sBs[off + 3] = __uint_as_float(f2tf32(v.w));
            }
        } else {
            // [k][n] : 32 rows x 128
#pragma unroll
            for (int i = 0; i < 4; i++) {
                int r  = (tid >> 5) + 8 * i;
                int c4 = (tid & 31) * 4;
                float4 v = *(const float4*)(Bb + (size_t)(k0 + r) * ldb + bn + c4);
                int off = r * 136 + c4;
                sBs[off + 0] = __uint_as_float(f2tf32(v.x));
                sBs[off + 1] = __uint_as_float(f2tf32(v.y));
                sBs[off + 2] = __uint_as_float(f2tf32(v.z));
                sBs[off + 3] = __uint_as_float(f2tf32(v.w));
            }
        }
        __syncthreads();

#pragma unroll
        for (int kk = 0; kk < 4; kk++) {
            const int kb = kk * 8;
            uint32_t a[4][4];
#pragma unroll
            for (int mt = 0; mt < 4; mt++) {
                int m0 = wm * 64 + mt * 16 + (lane >> 2);
                int kc = kb + (lane & 3);
                a[mt][0] = __float_as_uint(sAs[m0 * 36 + kc]);
                a[mt][1] = __float_as_uint(sAs[(m0 + 8) * 36 + kc]);
                a[mt][2] = __float_as_uint(sAs[m0 * 36 + kc + 4]);
                a[mt][3] = __float_as_uint(sAs[(m0 + 8) * 36 + kc + 4]);
            }
#pragma unroll
            for (int nt = 0; nt < 4; nt++) {
                int n0 = wn * 32 + nt * 8 + (lane >> 2);
                uint32_t b0, b1;
                if (NT) {
                    int kc = kb + (lane & 3);
                    b0 = __float_as_uint(sBs[n0 * 36 + kc]);
                    b1 = __float_as_uint(sBs[n0 * 36 + kc + 4]);
                } else {
                    int kr = kb + (lane & 3);
                    b0 = __float_as_uint(sBs[kr * 136 + n0]);
                    b1 = __float_as_uint(sBs[(kr + 4) * 136 + n0]);
                }
#pragma unroll
                for (int mt = 0; mt < 4; mt++)
                    mma8(acc[mt][nt], a[mt], b0, b1);
            }
        }
        __syncthreads();
    }

    // ---- Epilogue ----
#pragma unroll
    for (int nt = 0; nt < 4; nt++) {
        int col = bn + wn * 32 + nt * 8 + (lane & 3) * 2;
        float bv0 = 0.f, bv1 = 0.f;
        if (bias) { bv0 = bias[col]; bv1 = bias[col + 1]; }
#pragma unroll
        for (int mt = 0; mt < 4; mt++) {
            int r0 = bm + wm * 64 + mt * 16 + (lane >> 2);
            float v0 = acc[mt][nt][0] * scale + bv0;
            float v1 = acc[mt][nt][1] * scale + bv1;
            float v2 = acc[mt][nt][2] * scale + bv0;
            float v3 = acc[mt][nt][3] * scale + bv1;
            if (do_relu) {
                v0 = fmaxf(v0, 0.f); v1 = fmaxf(v1, 0.f);
                v2 = fmaxf(v2, 0.f); v3 = fmaxf(v3, 0.f);
            }
            *(float2*)(Cb + (size_t)r0 * ldc + col) = make_float2(v0, v1);
            *(float2*)(Cb + (size_t)(r0 + 8) * ldc + col) = make_float2(v2, v3);
        }
    }
}

// ---------------------------------------------------------------------------
// rel_key[b,t,s,h] = tanh(s_key[b,s,h] + t_key[b,t,h])
// ---------------------------------------------------------------------------
__global__ __launch_bounds__(256) void relkey_kernel(
    const float* __restrict__ skey, const float* __restrict__ tkey,
    float* __restrict__ rel)
{
    const size_t H4 = HD / 4;
    size_t idx = (size_t)blockIdx.x * blockDim.x + threadIdx.x;
    size_t h4 = idx % H4;
    size_t rest = idx / H4;
    int s = (int)(rest % SS); rest /= SS;
    int t = (int)(rest % TT);
    int b = (int)(rest / TT);
    float4 sv = ((const float4*)skey)[((size_t)b * SS + s) * H4 + h4];
    float4 tv = ((const float4*)tkey)[((size_t)b * TT + t) * H4 + h4];
    float4 o;
    o.x = tanhf(sv.x + tv.x);
    o.y = tanhf(sv.y + tv.y);
    o.z = tanhf(sv.z + tv.z);
    o.w = tanhf(sv.w + tv.w);
    ((float4*)rel)[idx] = o;
}

// ---------------------------------------------------------------------------
// Softmax over 4096 elements per row; one block (256 threads) per row.
// ---------------------------------------------------------------------------
__global__ __launch_bounds__(256) void softmax_kernel(float* __restrict__ data)
{
    float* row = data + (size_t)blockIdx.x * TSD;
    const int tid = threadIdx.x;
    float v[16];
    float m = -INFINITY;
#pragma unroll
    for (int i = 0; i < 16; i++) {
        v[i] = row[tid + i * 256];
        m = fmaxf(m, v[i]);
    }
#pragma unroll
    for (int o = 16; o; o >>= 1) m = fmaxf(m, __shfl_xor_sync(0xffffffffu, m, o));
    __shared__ float redm[8];
    __shared__ float reds[8];
    if ((tid & 31) == 0) redm[tid >> 5] = m;
    __syncthreads();
#pragma unroll
    for (int w = 0; w < 8; w++) m = fmaxf(m, redm[w]);
    float s = 0.f;
#pragma unroll
    for (int i = 0; i < 16; i++) {
        v[i] = expf(v[i] - m);
        s += v[i];
    }
#pragma unroll
    for (int o = 16; o; o >>= 1) s += __shfl_xor_sync(0xffffffffu, s, o);
    if ((tid & 31) == 0) reds[tid >> 5] = s;
    __syncthreads();
    s = 0.f;
#pragma unroll
    for (int w = 0; w < 8; w++) s += reds[w];
    float inv = 1.f / s;
#pragma unroll
    for (int i = 0; i < 16; i++) row[tid + i * 256] = v[i] * inv;
}

// Copy query into left half of concat buffer x (row stride XD).
__global__ __launch_bounds__(256) void concat_kernel(
    const float* __restrict__ q, float* __restrict__ x)
{
    const size_t Q4 = QD / 4;
    size_t idx = (size_t)blockIdx.x * blockDim.x + threadIdx.x;
    size_t rowi = idx / Q4;
    size_t c4 = idx % Q4;
    ((float4*)x)[rowi * (XD / 4) + c4] = ((const float4*)q)[idx];
}

// ---------------------------------------------------------------------------
extern "C" void kernel_launch(void* const* d_in, const int* in_sizes, int n_in,
                              void* d_out, int out_size)
{
    const float* query = (const float*)d_in[0];
    const float* src   = (const float*)d_in[1];
    const float* trg   = (const float*)d_in[2];
    const float* Wq    = (const float*)d_in[3];
    const float* b_q   = (const float*)d_in[4];
    const float* Ws    = (const float*)d_in[5];
    const float* b_s   = (const float*)d_in[6];
    const float* Wt    = (const float*)d_in[7];
    const float* b_t   = (const float*)d_in[8];
    const float* Wo    = (const float*)d_in[9];
    const float* b_o   = (const float*)d_in[10];
    float* out = (float*)d_out;

    float *q, *skey, *tkey, *rel, *scores, *x;
    cudaGetSymbolAddress((void**)&q, g_q);
    cudaGetSymbolAddress((void**)&skey, g_skey);
    cudaGetSymbolAddress((void**)&tkey, g_tkey);
    cudaGetSymbolAddress((void**)&rel, g_rel);
    cudaGetSymbolAddress((void**)&scores, g_scores);
    cudaGetSymbolAddress((void**)&x, g_x);

    const float inv_sqrt_h = 1.0f / sqrtf((float)HD);
    dim3 blk(256);

    // 1. q = query @ Wq + b_q            (8192 x 768 x 768)
    mma_gemm<false><<<dim3(HD / 128, (BB * LL) / 128, 1), blk>>>(
        query, QD, 0, Wq, HD, 0, b_q, q, HD, 0, QD, 1.f, 0);

    // 2. s_key = src @ Ws + b_s          (2048 x 768 x 1024)
    mma_gemm<false><<<dim3(HD / 128, (BB * SS) / 128, 1), blk>>>(
        src, FD, 0, Ws, HD, 0, b_s, skey, HD, 0, FD, 1.f, 0);

    // 3. t_key = trg @ Wt + b_t          (2048 x 768 x 1024)
    mma_gemm<false><<<dim3(HD / 128, (BB * TT) / 128, 1), blk>>>(
        trg, FD, 0, Wt, HD, 0, b_t, tkey, HD, 0, FD, 1.f, 0);

    // 4. rel_key = tanh(s_key[b,s,:] + t_key[b,t,:])
    {
        size_t n4 = (size_t)BB * TSD * HD / 4;
        relkey_kernel<<<(unsigned)(n4 / 256), blk>>>(skey, tkey, rel);
    }

    // 5. scores = q . rel^T / sqrt(H)    (batched: 256 x 4096 x 768, z=32)
    mma_gemm<true><<<dim3(TSD / 128, LL / 128, BB), blk>>>(
        q, HD, (size_t)LL * HD,
        rel, HD, (size_t)TSD * HD,
        nullptr,
        scores, TSD, (size_t)LL * TSD,
        HD, inv_sqrt_h, 0);

    // 6. softmax over 4096 per (b,l) row
    softmax_kernel<<<BB * LL, blk>>>(scores);

    // 7. x[:, :768] = query
    {
        size_t n4 = (size_t)BB * LL * QD / 4;
        concat_kernel<<<(unsigned)(n4 / 256), blk>>>(query, x);
    }

    // 8. x[:, 768:] = scores @ rel       (batched: 256 x 768 x 4096, z=32)
    mma_gemm<false><<<dim3(HD / 128, LL / 128, BB), blk>>>(
        scores, TSD, (size_t)LL * TSD,
        rel, HD, (size_t)TSD * HD,
        nullptr,
        x + QD, XD, (size_t)LL * XD,
        TSD, 1.f, 0);

    // 9. out = relu(x @ Wo + b_o)        (8192 x 768 x 1536)
    mma_gemm<false><<<dim3(OD / 128, (BB * LL) / 128, 1), blk>>>(
        x, XD, 0, Wo, OD, 0, b_o, out, OD, 0, XD, 1.f, 1);
}